// round 11
// baseline (speedup 1.0000x reference)
#include <cuda_runtime.h>
#include <cuda_fp16.h>
#include <cstdint>
#include <cstddef>

// Scratch: E = enc@W^T (2048x1024), D = dec@W^T + bias (512x1024)
__device__ float g_E[2048 * 1024];
__device__ float g_D[512 * 1024];

constexpr int KDIM = 512, NDIM = 1024;
constexpr int BM = 64, BN = 128, BK = 32;    // BK in floats; 16 half2 k-rows
constexpr int NKT = KDIM / BK;               // 16 k-tiles
constexpr int ASTR = 72;                     // mod 32 == 8 -> frag reads conflict-free
constexpr int BSTR = 136;

// fp16 mma m16n8k16, fp32 accumulate
__device__ __forceinline__ void mma_f16(float* c, const uint32_t* a, const uint32_t* b) {
    asm volatile(
        "mma.sync.aligned.m16n8k16.row.col.f32.f16.f16.f32 "
        "{%0,%1,%2,%3}, {%4,%5,%6,%7}, {%8,%9}, {%0,%1,%2,%3};\n"
        : "+f"(c[0]), "+f"(c[1]), "+f"(c[2]), "+f"(c[3])
        : "r"(a[0]), "r"(a[1]), "r"(a[2]), "r"(a[3]), "r"(b[0]), "r"(b[1]));
}

__device__ __forceinline__ uint32_t pack_h2(float x, float y) {
    __half2 h = __floats2half2_rn(x, y);
    return *reinterpret_cast<uint32_t*>(&h);
}

// ---------------------------------------------------------------------------
// fp16 tensor-core NT GEMM, occupancy retile: 64x128 CTA tile, 256 threads,
// 8 warps (2x4), warp tile 32x32 -> acc 32 regs -> ~3 CTAs/SM.
// grid = (8, 40): y<32 -> E row-tiles (enc), else D row-tiles (dec, +bias).
// ---------------------------------------------------------------------------
__global__ void __launch_bounds__(256)
gemm_f16(const float* __restrict__ enc, const float* __restrict__ dec,
         const float* __restrict__ W, const float* __restrict__ bias,
         float* __restrict__ E, float* __restrict__ D)
{
    __shared__ uint32_t As[BK / 2][ASTR];    // [k2][m] packed half2
    __shared__ uint32_t Bs[BK / 2][BSTR];    // [k2][n]

    const int tid  = threadIdx.x;
    const int col0 = blockIdx.x * BN;
    const bool isE = (blockIdx.y < 32);
    const int row0 = isE ? blockIdx.y * BM : (blockIdx.y - 32) * BM;
    const float* A = isE ? enc : dec;
    float* C       = isE ? E : D;

    // A staging: 4 thr/row (64 rows), each covers 8 floats (2 float4)
    const int arow = tid >> 2;
    const int akq  = (tid & 3) * 8;
    // B staging: 2 thr/row (128 rows), each covers 16 floats (4 float4)
    const int brow = tid >> 1;
    const int bkq  = (tid & 1) * 16;

    const float* aptr = A + (size_t)(row0 + arow) * KDIM + akq;
    const float* bptr = W + (size_t)(col0 + brow) * KDIM + bkq;

    const int lane = tid & 31, warp = tid >> 5;
    const int g = lane >> 2, tig = lane & 3;
    const int wm = (warp >> 2) * 32, wn = (warp & 3) * 32;

    float acc[2][4][4];
#pragma unroll
    for (int mf = 0; mf < 2; mf++)
#pragma unroll
        for (int nf = 0; nf < 4; nf++)
#pragma unroll
            for (int i = 0; i < 4; i++) acc[mf][nf][i] = 0.f;

    float4 pa[2], pb[4];
#pragma unroll
    for (int j = 0; j < 2; j++) pa[j] = *(const float4*)(aptr + j * 4);
#pragma unroll
    for (int j = 0; j < 4; j++) pb[j] = *(const float4*)(bptr + j * 4);

    for (int kt = 0; kt < NKT; kt++) {
        // stage prefetched tile (pack to half2 along K)
#pragma unroll
        for (int j = 0; j < 2; j++) {
            As[(akq >> 1) + j * 2 + 0][arow] = pack_h2(pa[j].x, pa[j].y);
            As[(akq >> 1) + j * 2 + 1][arow] = pack_h2(pa[j].z, pa[j].w);
        }
#pragma unroll
        for (int j = 0; j < 4; j++) {
            Bs[(bkq >> 1) + j * 2 + 0][brow] = pack_h2(pb[j].x, pb[j].y);
            Bs[(bkq >> 1) + j * 2 + 1][brow] = pack_h2(pb[j].z, pb[j].w);
        }
        __syncthreads();

        if (kt + 1 < NKT) {                  // prefetch next tile
            aptr += BK; bptr += BK;
#pragma unroll
            for (int j = 0; j < 2; j++) pa[j] = *(const float4*)(aptr + j * 4);
#pragma unroll
            for (int j = 0; j < 4; j++) pb[j] = *(const float4*)(bptr + j * 4);
        }

        // 2 k16-steps per tile
#pragma unroll
        for (int ks = 0; ks < 2; ks++) {
            const int k8 = ks * 8;
            uint32_t af[2][4], bf[4][2];
#pragma unroll
            for (int mf = 0; mf < 2; mf++) {
                const int m = wm + mf * 16 + g;
                af[mf][0] = As[k8 + tig][m];
                af[mf][1] = As[k8 + tig][m + 8];
                af[mf][2] = As[k8 + tig + 4][m];
                af[mf][3] = As[k8 + tig + 4][m + 8];
            }
#pragma unroll
            for (int nf = 0; nf < 4; nf++) {
                const int n = wn + nf * 8 + g;
                bf[nf][0] = Bs[k8 + tig][n];
                bf[nf][1] = Bs[k8 + tig + 4][n];
            }
#pragma unroll
            for (int mf = 0; mf < 2; mf++)
#pragma unroll
                for (int nf = 0; nf < 4; nf++)
                    mma_f16(acc[mf][nf], af[mf], bf[nf]);
        }
        __syncthreads();
    }

    // epilogue (+ bias for D)
    float2 bv[4];
#pragma unroll
    for (int nf = 0; nf < 4; nf++) {
        if (isE) bv[nf] = make_float2(0.f, 0.f);
        else     bv[nf] = *(const float2*)(bias + col0 + wn + nf * 8 + tig * 2);
    }
#pragma unroll
    for (int mf = 0; mf < 2; mf++) {
        const int r = row0 + wm + mf * 16 + g;
#pragma unroll
        for (int nf = 0; nf < 4; nf++) {
            const int c = col0 + wn + nf * 8 + tig * 2;
            float2 v0 = make_float2(acc[mf][nf][0] + bv[nf].x,
                                    acc[mf][nf][1] + bv[nf].y);
            float2 v1 = make_float2(acc[mf][nf][2] + bv[nf].x,
                                    acc[mf][nf][3] + bv[nf].y);
            *(float2*)(C + (size_t)r * NDIM + c)       = v0;
            *(float2*)(C + (size_t)(r + 8) * NDIM + c) = v1;
        }
    }
}

// ---------------------------------------------------------------------------
// Broadcast add (R8, measured 87.8-89.8us, at write-BW floor): unchanged.
// out[b,t,u,v] = E[b*256+t, v] + D[b*64+u, v]
// ---------------------------------------------------------------------------
__global__ void __launch_bounds__(256)
bcast_add(const float* __restrict__ E, const float* __restrict__ D,
          float* __restrict__ out)
{
    const int tile = blockIdx.x;            // 0..2047
    const int b    = tile >> 8;
    const int t    = tile & 255;
    const int v4   = threadIdx.x;

    const float4* E4 = (const float4*)E;
    const float4* D4 = (const float4*)D;
    float4*       O4 = (float4*)out;

    const float4 e = E4[(size_t)(b * 256 + t) * 256 + v4];
    const size_t base = ((size_t)(b * 256 + t) * 64) * 256 + v4;
    const float4* Dp  = D4 + (size_t)(b * 64) * 256 + v4;

    for (int u = 0; u < 64; u += 4) {
        float4 d0 = __ldg(Dp + (size_t)(u + 0) * 256);
        float4 d1 = __ldg(Dp + (size_t)(u + 1) * 256);
        float4 d2 = __ldg(Dp + (size_t)(u + 2) * 256);
        float4 d3 = __ldg(Dp + (size_t)(u + 3) * 256);

        const size_t o = base + (size_t)u * 256;
        O4[o]           = make_float4(e.x + d0.x, e.y + d0.y, e.z + d0.z, e.w + d0.w);
        O4[o + 256]     = make_float4(e.x + d1.x, e.y + d1.y, e.z + d1.z, e.w + d1.w);
        O4[o + 2 * 256] = make_float4(e.x + d2.x, e.y + d2.y, e.z + d2.z, e.w + d2.w);
        O4[o + 3 * 256] = make_float4(e.x + d3.x, e.y + d3.y, e.z + d3.z, e.w + d3.w);
    }
}

// ---------------------------------------------------------------------------
extern "C" void kernel_launch(void* const* d_in, const int* in_sizes, int n_in,
                              void* d_out, int out_size) {
    const float* enc  = (const float*)d_in[0];  // (8,256,512)
    const float* dec  = (const float*)d_in[1];  // (8,64,512)
    const float* W    = (const float*)d_in[2];  // (1024,512)
    const float* bias = (const float*)d_in[3];  // (1024,)
    float* out = (float*)d_out;                 // (8,256,64,1024)

    float *E, *D;
    cudaGetSymbolAddress((void**)&E, g_E);
    cudaGetSymbolAddress((void**)&D, g_D);

    gemm_f16<<<dim3(NDIM / BN, 40), 256>>>(enc, dec, W, bias, E, D);
    bcast_add<<<2048, 256>>>(E, D, out);
}